// round 9
// baseline (speedup 1.0000x reference)
#include <cuda_runtime.h>
#include <math.h>

#define BB 64
#define SS 128
#define FF 16
#define HH 64
#define G4H 256
#define QN 192

typedef unsigned long long ull;

// packed fp32x2 helpers (sm_103a FFMA2 path)
#define FMA_F32X2(d, a, b, c) \
    asm("fma.rn.f32x2 %0, %1, %2, %3;" : "=l"(d) : "l"(a), "l"(b), "l"(c))
#define PACK_F32X2U(out, lo, hi) \
    asm("mov.b64 %0, {%1, %2};" : "=l"(out) : "r"(lo), "r"(hi))
#define UNPACK_F32X2U(lo, hi, in) \
    asm("mov.b64 {%0, %1}, %2;" : "=r"(lo), "=r"(hi) : "l"(in))

__device__ __forceinline__ float hsum2(ull v) {
    unsigned int lo, hi;
    UNPACK_F32X2U(lo, hi, v);
    return __uint_as_float(lo) + __uint_as_float(hi);
}
__device__ __forceinline__ ull pack_f2(float lo, float hi) {
    ull r;
    PACK_F32X2U(r, __float_as_uint(lo), __float_as_uint(hi));
    return r;
}

// ---------------- scratch (static device globals; no allocation) -------------
__device__ float g_lstm[2][FF][BB][SS][HH];      // 67 MB
__device__ float g_comb[BB][2 * FF * HH];        // 512 KB

// ---------------- helpers ----------------------------------------------------
__device__ __forceinline__ float sigm_f(float x) {
    return __fdividef(1.f, 1.f + __expf(-x));
}
__device__ __forceinline__ float tanh_f(float x) {
    x = fminf(fmaxf(x, -10.f), 10.f);
    float e = __expf(2.f * x);
    return __fdividef(e - 1.f, e + 1.f);
}

// ---------------- LSTM kernel ------------------------------------------------
// grid (16, 16, 2): batch-chunk of 4, feature, branch. 256 threads.
// Weight pairs register-resident as f32x2; gates GEMM in packed FFMA2.
#define LCH 4

__global__ void __launch_bounds__(256, 2) lstm_kernel(
    const float* __restrict__ x0, const float* __restrict__ x1,
    const float* __restrict__ Wih0, const float* __restrict__ Whh0,
    const float* __restrict__ bih0, const float* __restrict__ bhh0,
    const float* __restrict__ Wih1, const float* __restrict__ Whh1,
    const float* __restrict__ bih1, const float* __restrict__ bhh1)
{
    __shared__ float h_sh[LCH * 64];
    __shared__ float c_sh[LCH * 64];
    __shared__ float g_sh[LCH * 256];
    __shared__ float xs[LCH];

    const int t  = threadIdx.x;                 // gate index
    const int f  = blockIdx.y;
    const int b0 = blockIdx.x * LCH;
    const int br = blockIdx.z;

    const float* x   = br ? x1   : x0;
    const float* Wih = br ? Wih1 : Wih0;
    const float* Whh = br ? Whh1 : Whh0;
    const float* bih = br ? bih1 : bih0;
    const float* bhh = br ? bhh1 : bhh0;

    // register-resident Whh row for gate t: 32 packed (w_j, w_{j+1}) pairs
    ull w2[32];
    {
        const ulonglong2* wrow = (const ulonglong2*)(Whh + (f * G4H + t) * HH);
        #pragma unroll
        for (int c = 0; c < 16; c++) {
            ulonglong2 v = wrow[c];
            w2[2 * c]     = v.x;
            w2[2 * c + 1] = v.y;
        }
    }

    const float wih_r  = Wih[f * G4H + t];
    const float bias_r = bih[f * G4H + t] + bhh[f * G4H + t];

    for (int i = t; i < LCH * 64; i += 256) { h_sh[i] = 0.f; c_sh[i] = 0.f; }
    if (t < LCH) xs[t] = x[((b0 + t) * SS + 0) * FF + f];
    __syncthreads();

    float* outbase = &g_lstm[br][f][b0][0][0];   // [LCH][S][H] slab
    const int bb = t >> 6, jj = t & 63;          // epilogue cell

    float xnext = 0.f;
    for (int s = 0; s < SS; s++) {
        // prefetch next step's x (latency hidden under the gates GEMM)
        if (t < LCH && s + 1 < SS) xnext = x[((b0 + t) * SS + s + 1) * FF + f];

        // packed partial accumulators over j-parity; init bias into lane 0
        ull acc2[LCH];
        #pragma unroll
        for (int b = 0; b < LCH; b++)
            acc2[b] = pack_f2(fmaf(xs[b], wih_r, bias_r), 0.f);

        #pragma unroll
        for (int jc = 0; jc < 16; jc++) {
            ull wlo = w2[2 * jc], whi = w2[2 * jc + 1];
            #pragma unroll
            for (int b = 0; b < LCH; b++) {
                // (h_j, h_j+1, h_j+2, h_j+3) for batch b — broadcast 16B
                ulonglong2 hv = *(const ulonglong2*)(h_sh + b * 64 + jc * 4);
                FMA_F32X2(acc2[b], hv.x, wlo, acc2[b]);
                FMA_F32X2(acc2[b], hv.y, whi, acc2[b]);
            }
        }
        #pragma unroll
        for (int b = 0; b < LCH; b++) g_sh[b * 256 + t] = hsum2(acc2[b]);
        __syncthreads();

        // epilogue: one cell per thread
        {
            float gi = g_sh[bb * 256 + jj];
            float gf = g_sh[bb * 256 + 64 + jj];
            float gg = g_sh[bb * 256 + 128 + jj];
            float go = g_sh[bb * 256 + 192 + jj];
            float cc = sigm_f(gf) * c_sh[bb * 64 + jj] + sigm_f(gi) * tanh_f(gg);
            float hh = sigm_f(go) * tanh_f(cc);
            c_sh[bb * 64 + jj] = cc;
            h_sh[bb * 64 + jj] = hh;
            outbase[(bb * SS + s) * HH + jj] = hh;
        }
        if (t < LCH) xs[t] = xnext;
        __syncthreads();
    }
}

// ---------------- fused QK + attention core (V eliminated) -------------------
// block per (b, f, branch), 512 threads, 1 CTA/SM. Packed FFMA2 in the
// QK GEMM and score loops (pairs over the K/d reduction axis).
#define XPAD 68
#define ATTN_SMEM ((2*128*XPAD + 32*128 + 128 + 64 + 64) * 4)

__global__ void __launch_bounds__(512, 1) attn_kernel(
    const float* __restrict__ Wq0, const float* __restrict__ bq0,
    const float* __restrict__ Wo0, const float* __restrict__ bo0,
    const float* __restrict__ Wq1, const float* __restrict__ bq1,
    const float* __restrict__ Wo1, const float* __restrict__ bo1,
    float* __restrict__ d_out)
{
    extern __shared__ float sm[];
    float* Xs   = sm;                      // [128][68]   (phase 1)
    float* Wsh  = sm + 128 * XPAD;         // [128][68]   (phase 1)
    float* Qs   = sm;                      // [128][68]   (phase 2, aliases Xs)
    float* Ks   = sm + 128 * XPAD;         // [128][68]   (phase 2, aliases Wsh)
    float* psum = sm + 2 * 128 * XPAD;     // [32][128]
    float* pbar = psum + 32 * 128;         // [128]
    float* ys   = pbar + 128;              // [64]
    float* obar = ys + 64;                 // [64]

    const int tid = threadIdx.x;
    const int tx = tid & 15, ty = tid >> 4;   // ty: 0..31
    const int b = blockIdx.x, f = blockIdx.y, br = blockIdx.z;

    const float* Wq   = br ? Wq1 : Wq0;
    const float* bq   = br ? bq1 : bq0;
    const float* Wout = br ? Wo1 : Wo0;
    const float* bout = br ? bo1 : bo0;

    const float* Xg = &g_lstm[br][f][b][0][0];     // [128][64] in gmem

    // ---- stage X [128][64] and Wqk [128][64] ----
    const float4* X4 = (const float4*)Xg;
    #pragma unroll
    for (int l = 0; l < 4; l++) {
        int li = tid + l * 512;              // 0..2047
        int s = li >> 4, c4 = li & 15;
        *(float4*)&Xs[s * XPAD + c4 * 4] = X4[li];
    }
    const float4* W4 = (const float4*)(Wq + (size_t)f * QN * HH);
    #pragma unroll
    for (int l = 0; l < 4; l++) {
        int li = tid + l * 512;              // rows 0..127 (Q,K)
        int g = li >> 4, c4 = li & 15;
        *(float4*)&Wsh[g * XPAD + c4 * 4] = W4[li];
    }
    __syncthreads();

    // ---- QK GEMM: [128 rows][128 gate-cols], packed over k-parity ----
    ull acc2[4][8];
    {
        #pragma unroll
        for (int j = 0; j < 8; j++) {
            float bj = bq[f * QN + tx + 16 * j];
            #pragma unroll
            for (int i = 0; i < 4; i++) acc2[i][j] = pack_f2(bj, 0.f);
        }
        #pragma unroll
        for (int k4 = 0; k4 < 16; k4++) {
            ull w01[8], w23[8];
            #pragma unroll
            for (int j = 0; j < 8; j++) {
                ulonglong2 wv = *(const ulonglong2*)&Wsh[(tx + 16 * j) * XPAD + k4 * 4];
                w01[j] = wv.x; w23[j] = wv.y;
            }
            #pragma unroll
            for (int i = 0; i < 4; i++) {
                ulonglong2 xv = *(const ulonglong2*)&Xs[(ty * 4 + i) * XPAD + k4 * 4];
                #pragma unroll
                for (int j = 0; j < 8; j++) {
                    FMA_F32X2(acc2[i][j], xv.x, w01[j], acc2[i][j]);
                    FMA_F32X2(acc2[i][j], xv.y, w23[j], acc2[i][j]);
                }
            }
        }
    }
    __syncthreads();   // ALL reads of Xs/Wsh complete before aliased writes
    #pragma unroll
    for (int i = 0; i < 4; i++) {
        int s = ty * 4 + i;
        #pragma unroll
        for (int j = 0; j < 4; j++) Qs[s * XPAD + tx + 16 * j] = hsum2(acc2[i][j]);
        #pragma unroll
        for (int j = 4; j < 8; j++) Ks[s * XPAD + tx + 16 * (j - 4)] = hsum2(acc2[i][j]);
    }
    __syncthreads();

    float* attn_base = d_out + 128 + (size_t)br * FF * BB * SS * SS
                     + ((size_t)(f * BB + b)) * SS * SS;
    const float scale = 0.17677669529663687f;  // 1/sqrt(32)

    float p0[4][8];                    // head-0 probs in regs

    for (int n = 0; n < 2; n++) {
        const int off = n * 32;
        ull c2[4][8];
        #pragma unroll
        for (int i = 0; i < 4; i++)
            #pragma unroll
            for (int j = 0; j < 8; j++) c2[i][j] = 0ULL;

        // packed over d-parity: 8 × 16B chunks of the 32-dim head
        #pragma unroll
        for (int d4 = 0; d4 < 8; d4++) {
            ull k01[8], k23[8];
            #pragma unroll
            for (int j = 0; j < 8; j++) {
                ulonglong2 kv = *(const ulonglong2*)&Ks[(tx + 16 * j) * XPAD + off + d4 * 4];
                k01[j] = kv.x; k23[j] = kv.y;
            }
            #pragma unroll
            for (int i = 0; i < 4; i++) {
                ulonglong2 qv = *(const ulonglong2*)&Qs[(ty * 4 + i) * XPAD + off + d4 * 4];
                #pragma unroll
                for (int j = 0; j < 8; j++) {
                    FMA_F32X2(c2[i][j], qv.x, k01[j], c2[i][j]);
                    FMA_F32X2(c2[i][j], qv.y, k23[j], c2[i][j]);
                }
            }
        }

        float c[4][8];
        #pragma unroll
        for (int i = 0; i < 4; i++)
            #pragma unroll
            for (int j = 0; j < 8; j++) c[i][j] = hsum2(c2[i][j]);

        // scale + row softmax (row = 16 lanes of one half-warp)
        #pragma unroll
        for (int i = 0; i < 4; i++) {
            float m = c[i][0] * scale;
            #pragma unroll
            for (int j = 0; j < 8; j++) { c[i][j] *= scale; m = fmaxf(m, c[i][j]); }
            #pragma unroll
            for (int o = 8; o >= 1; o >>= 1)
                m = fmaxf(m, __shfl_xor_sync(0xffffffffu, m, o, 16));
            float s2 = 0.f;
            #pragma unroll
            for (int j = 0; j < 8; j++) { c[i][j] = __expf(c[i][j] - m); s2 += c[i][j]; }
            #pragma unroll
            for (int o = 8; o >= 1; o >>= 1)
                s2 += __shfl_xor_sync(0xffffffffu, s2, o, 16);
            float inv = __fdividef(1.f, s2);
            #pragma unroll
            for (int j = 0; j < 8; j++) c[i][j] *= inv;
        }

        // head-mean probs: head0 in regs, single store at head1
        float colsum[8];
        #pragma unroll
        for (int j = 0; j < 8; j++) colsum[j] = 0.f;
        #pragma unroll
        for (int i = 0; i < 4; i++) {
            float* ab = attn_base + (ty * 4 + i) * SS;
            #pragma unroll
            for (int j = 0; j < 8; j++) {
                float p = c[i][j];
                colsum[j] += p;
                if (n == 0) p0[i][j] = p;
                else        ab[tx + 16 * j] = 0.5f * (p0[i][j] + p);
            }
        }
        #pragma unroll
        for (int j = 0; j < 8; j++) psum[ty * 128 + tx + 16 * j] = colsum[j];
        __syncthreads();

        if (tid < 128) {
            float s2 = 0.f;
            #pragma unroll
            for (int yy = 0; yy < 32; yy++) s2 += psum[yy * 128 + tid];
            pbar[tid] = s2 * (1.f / 128.f);
        }
        __syncthreads();

        // y = pbar @ X   (X re-read from gmem, L2-hot; dual accumulators)
        if (tid < 64) {
            float a2 = 0.f, a3 = 0.f;
            #pragma unroll 8
            for (int k = 0; k < 128; k += 2) {
                a2 = fmaf(pbar[k],     Xg[k * HH + tid],       a2);
                a3 = fmaf(pbar[k + 1], Xg[(k + 1) * HH + tid], a3);
            }
            ys[tid] = a2 + a3;
        }
        __syncthreads();

        // obar[head cols] = y @ Wv^T + bv   (Wv rows from gmem, L2-hot)
        if (tid < 32) {
            float a2 = bq[f * QN + 128 + off + tid];
            const float4* wr = (const float4*)(Wq + ((size_t)f * QN + 128 + off + tid) * HH);
            #pragma unroll
            for (int d4 = 0; d4 < 16; d4++) {
                float4 wv = wr[d4];
                a2 = fmaf(ys[d4 * 4 + 0], wv.x, a2);
                a2 = fmaf(ys[d4 * 4 + 1], wv.y, a2);
                a2 = fmaf(ys[d4 * 4 + 2], wv.z, a2);
                a2 = fmaf(ys[d4 * 4 + 3], wv.w, a2);
            }
            obar[off + tid] = a2;
        }
        __syncthreads();
    }

    // pooled = obar @ Wout^T + bout   (Wout rows from gmem, L2-hot)
    if (tid < 64) {
        float a2 = bout[f * 64 + tid];
        const float4* wr = (const float4*)(Wout + (size_t)f * 64 * 64 + tid * 64);
        #pragma unroll
        for (int h4 = 0; h4 < 16; h4++) {
            float4 wv = wr[h4];
            a2 = fmaf(obar[h4 * 4 + 0], wv.x, a2);
            a2 = fmaf(obar[h4 * 4 + 1], wv.y, a2);
            a2 = fmaf(obar[h4 * 4 + 2], wv.z, a2);
            a2 = fmaf(obar[h4 * 4 + 3], wv.w, a2);
        }
        g_comb[b][br * (FF * HH) + f * HH + tid] = a2;
    }
}

// ---------------- final: static/time MLPs + fc --------------------------------
__global__ void final_kernel(
    const float* __restrict__ stat,  // [B,32]
    const float* __restrict__ tg,    // [B,1]
    const float* __restrict__ d1w, const float* __restrict__ d1b,
    const float* __restrict__ d2w, const float* __restrict__ d2b,
    const float* __restrict__ t1w, const float* __restrict__ t1b,
    const float* __restrict__ t2w, const float* __restrict__ t2b,
    const float* __restrict__ fcw, const float* __restrict__ fcb,
    float* __restrict__ out)
{
    __shared__ float s1[64], t1s[16], tail[40], red[2][128];
    const int b = blockIdx.x, t = threadIdx.x;  // 128 threads

    if (t < 64) {
        float a = d1b[t];
        #pragma unroll
        for (int i = 0; i < 32; i++) a = fmaf(stat[b * 32 + i], d1w[t * 32 + i], a);
        s1[t] = fmaxf(a, 0.f);
    }
    if (t < 16) t1s[t] = fmaxf(fmaf(tg[b], t1w[t], t1b[t]), 0.f);
    __syncthreads();
    if (t < 32) {
        float a = d2b[t];
        #pragma unroll
        for (int i = 0; i < 64; i++) a = fmaf(s1[i], d2w[t * 64 + i], a);
        tail[t] = fmaxf(a, 0.f);
    }
    if (t >= 32 && t < 40) {
        int j = t - 32;
        float a = t2b[j];
        #pragma unroll
        for (int i = 0; i < 16; i++) a = fmaf(t1s[i], t2w[j * 16 + i], a);
        tail[t] = fmaxf(a, 0.f);
    }
    __syncthreads();

    float a0 = 0.f, a1 = 0.f;
    for (int c = t; c < 2088; c += 128) {
        float v = (c < 2048) ? g_comb[b][c] : tail[c - 2048];
        a0 = fmaf(v, fcw[c], a0);
        a1 = fmaf(v, fcw[2088 + c], a1);
    }
    red[0][t] = a0; red[1][t] = a1;
    __syncthreads();
    for (int off = 64; off >= 1; off >>= 1) {
        if (t < off) { red[0][t] += red[0][t + off]; red[1][t] += red[1][t + off]; }
        __syncthreads();
    }
    if (t == 0) {
        out[b * 2 + 0] = red[0][0] + fcb[0];
        out[b * 2 + 1] = red[1][0] + fcb[1];
    }
}

// ---------------- launch ------------------------------------------------------
extern "C" void kernel_launch(void* const* d_in, const int* in_sizes, int n_in,
                              void* d_out, int out_size)
{
    (void)in_sizes; (void)n_in; (void)out_size;
    float* out = (float*)d_out;

    cudaFuncSetAttribute(attn_kernel, cudaFuncAttributeMaxDynamicSharedMemorySize, ATTN_SMEM);

    // LSTM: both branches, batch-chunk 4
    lstm_kernel<<<dim3(16, 16, 2), 256>>>(
        (const float*)d_in[0], (const float*)d_in[1],
        (const float*)d_in[4], (const float*)d_in[5],
        (const float*)d_in[6], (const float*)d_in[7],
        (const float*)d_in[8], (const float*)d_in[9],
        (const float*)d_in[10], (const float*)d_in[11]);

    // fused QK + attention (V eliminated algebraically), both branches
    attn_kernel<<<dim3(64, 16, 2), 512, ATTN_SMEM>>>(
        (const float*)d_in[12], (const float*)d_in[13],
        (const float*)d_in[14], (const float*)d_in[15],
        (const float*)d_in[16], (const float*)d_in[17],
        (const float*)d_in[18], (const float*)d_in[19],
        out);

    // final MLPs + fc
    final_kernel<<<64, 128>>>(
        (const float*)d_in[2], (const float*)d_in[3],
        (const float*)d_in[20], (const float*)d_in[21],
        (const float*)d_in[22], (const float*)d_in[23],
        (const float*)d_in[24], (const float*)d_in[25],
        (const float*)d_in[26], (const float*)d_in[27],
        (const float*)d_in[28], (const float*)d_in[29],
        out);
}

// round 13
// speedup vs baseline: 1.6097x; 1.6097x over previous
#include <cuda_runtime.h>
#include <math.h>

#define BB 64
#define SS 128
#define FF 16
#define HH 64
#define G4H 256
#define QN 192

// ---------------- scratch (static device globals; no allocation) -------------
__device__ float g_lstm[2][FF][BB][SS][HH];      // 67 MB
__device__ float g_comb[BB][2 * FF * HH];        // 512 KB

// ---------------- helpers ----------------------------------------------------
__device__ __forceinline__ float sigm_f(float x) {
    return __fdividef(1.f, 1.f + __expf(-x));
}
__device__ __forceinline__ float tanh_f(float x) {
    x = fminf(fmaxf(x, -10.f), 10.f);
    float e = __expf(2.f * x);
    return __fdividef(e - 1.f, e + 1.f);
}

// ---------------- LSTM kernel ------------------------------------------------
// grid (8, 16, 2): batch-chunk of 8, feature, branch. 256 threads.
// 256 CTAs at 2 CTAs/SM = ONE wave (no tail). Weights register-resident.
#define LCH 8

__global__ void __launch_bounds__(256, 2) lstm_kernel(
    const float* __restrict__ x0, const float* __restrict__ x1,
    const float* __restrict__ Wih0, const float* __restrict__ Whh0,
    const float* __restrict__ bih0, const float* __restrict__ bhh0,
    const float* __restrict__ Wih1, const float* __restrict__ Whh1,
    const float* __restrict__ bih1, const float* __restrict__ bhh1)
{
    __shared__ float h_sh[LCH * 64];
    __shared__ float c_sh[LCH * 64];
    __shared__ float g_sh[LCH * 256];
    __shared__ float xs[LCH];

    const int t  = threadIdx.x;                 // gate index
    const int f  = blockIdx.y;
    const int b0 = blockIdx.x * LCH;
    const int br = blockIdx.z;

    const float* x   = br ? x1   : x0;
    const float* Wih = br ? Wih1 : Wih0;
    const float* Whh = br ? Whh1 : Whh0;
    const float* bih = br ? bih1 : bih0;
    const float* bhh = br ? bhh1 : bhh0;

    // register-resident Whh row for gate t (64 floats)
    float4 w[16];
    const float4* wrow = (const float4*)(Whh + (f * G4H + t) * HH);
    #pragma unroll
    for (int c = 0; c < 16; c++) w[c] = wrow[c];

    const float wih_r  = Wih[f * G4H + t];
    const float bias_r = bih[f * G4H + t] + bhh[f * G4H + t];

    for (int i = t; i < LCH * 64; i += 256) { h_sh[i] = 0.f; c_sh[i] = 0.f; }
    if (t < LCH) xs[t] = x[((b0 + t) * SS + 0) * FF + f];
    __syncthreads();

    float* outbase = &g_lstm[br][f][b0][0][0];   // [LCH][S][H] slab

    float xnext = 0.f;
    for (int s = 0; s < SS; s++) {
        // prefetch next step's x (latency hidden under the gates GEMM)
        if (t < LCH && s + 1 < SS) xnext = x[((b0 + t) * SS + s + 1) * FF + f];

        float acc[LCH];
        #pragma unroll
        for (int b = 0; b < LCH; b++) acc[b] = fmaf(xs[b], wih_r, bias_r);

        const float4* h4 = (const float4*)h_sh;
        #pragma unroll
        for (int hc = 0; hc < 16; hc++) {
            float4 wv = w[hc];
            #pragma unroll
            for (int b = 0; b < LCH; b++) {
                float4 hv = h4[b * 16 + hc];     // broadcast
                acc[b] = fmaf(wv.x, hv.x, acc[b]);
                acc[b] = fmaf(wv.y, hv.y, acc[b]);
                acc[b] = fmaf(wv.z, hv.z, acc[b]);
                acc[b] = fmaf(wv.w, hv.w, acc[b]);
            }
        }
        #pragma unroll
        for (int b = 0; b < LCH; b++) g_sh[b * 256 + t] = acc[b];
        __syncthreads();

        // epilogue: 512 cells, 2 per thread
        #pragma unroll
        for (int ci = 0; ci < 2; ci++) {
            int idx = t + ci * 256;
            int bb = idx >> 6;
            int jj = idx & 63;
            float gi = g_sh[bb * 256 + jj];
            float gf = g_sh[bb * 256 + 64 + jj];
            float gg = g_sh[bb * 256 + 128 + jj];
            float go = g_sh[bb * 256 + 192 + jj];
            float cc = sigm_f(gf) * c_sh[bb * 64 + jj] + sigm_f(gi) * tanh_f(gg);
            float hh = sigm_f(go) * tanh_f(cc);
            c_sh[bb * 64 + jj] = cc;
            h_sh[bb * 64 + jj] = hh;
            outbase[(bb * SS + s) * HH + jj] = hh;
        }
        if (t < LCH) xs[t] = xnext;
        __syncthreads();
    }
}

// ---------------- fused QK + attention core (V eliminated) -------------------
// block per (b, f, branch), 512 threads, 1 CTA/SM (R8-passing form).
#define XPAD 68
#define ATTN_SMEM ((2*128*XPAD + 32*128 + 128 + 64 + 64) * 4)

__global__ void __launch_bounds__(512, 1) attn_kernel(
    const float* __restrict__ Wq0, const float* __restrict__ bq0,
    const float* __restrict__ Wo0, const float* __restrict__ bo0,
    const float* __restrict__ Wq1, const float* __restrict__ bq1,
    const float* __restrict__ Wo1, const float* __restrict__ bo1,
    float* __restrict__ d_out)
{
    extern __shared__ float sm[];
    float* Xs   = sm;                      // [128][68]   (phase 1)
    float* Wsh  = sm + 128 * XPAD;         // [128][68]   (phase 1)
    float* Qs   = sm;                      // [128][68]   (phase 2, aliases Xs)
    float* Ks   = sm + 128 * XPAD;         // [128][68]   (phase 2, aliases Wsh)
    float* psum = sm + 2 * 128 * XPAD;     // [32][128]
    float* pbar = psum + 32 * 128;         // [128]
    float* ys   = pbar + 128;              // [64]
    float* obar = ys + 64;                 // [64]

    const int tid = threadIdx.x;
    const int tx = tid & 15, ty = tid >> 4;   // ty: 0..31
    const int b = blockIdx.x, f = blockIdx.y, br = blockIdx.z;

    const float* Wq   = br ? Wq1 : Wq0;
    const float* bq   = br ? bq1 : bq0;
    const float* Wout = br ? Wo1 : Wo0;
    const float* bout = br ? bo1 : bo0;

    const float* Xg = &g_lstm[br][f][b][0][0];     // [128][64] in gmem

    // ---- stage X [128][64] and Wqk [128][64] ----
    const float4* X4 = (const float4*)Xg;
    #pragma unroll
    for (int l = 0; l < 4; l++) {
        int li = tid + l * 512;              // 0..2047
        int s = li >> 4, c4 = li & 15;
        *(float4*)&Xs[s * XPAD + c4 * 4] = X4[li];
    }
    const float4* W4 = (const float4*)(Wq + (size_t)f * QN * HH);
    #pragma unroll
    for (int l = 0; l < 4; l++) {
        int li = tid + l * 512;              // rows 0..127 (Q,K)
        int g = li >> 4, c4 = li & 15;
        *(float4*)&Wsh[g * XPAD + c4 * 4] = W4[li];
    }
    __syncthreads();

    // ---- QK GEMM: [128 rows][128 gate-cols], acc held across the barrier ----
    float acc[4][8];
    {
        #pragma unroll
        for (int j = 0; j < 8; j++) {
            float bj = bq[f * QN + tx + 16 * j];
            #pragma unroll
            for (int i = 0; i < 4; i++) acc[i][j] = bj;
        }
        #pragma unroll
        for (int k4 = 0; k4 < 16; k4++) {
            float4 wv[8];
            #pragma unroll
            for (int j = 0; j < 8; j++)
                wv[j] = *(const float4*)&Wsh[(tx + 16 * j) * XPAD + k4 * 4];
            #pragma unroll
            for (int i = 0; i < 4; i++) {
                float4 xv = *(const float4*)&Xs[(ty * 4 + i) * XPAD + k4 * 4];
                #pragma unroll
                for (int j = 0; j < 8; j++) {
                    acc[i][j] = fmaf(xv.x, wv[j].x, acc[i][j]);
                    acc[i][j] = fmaf(xv.y, wv[j].y, acc[i][j]);
                    acc[i][j] = fmaf(xv.z, wv[j].z, acc[i][j]);
                    acc[i][j] = fmaf(xv.w, wv[j].w, acc[i][j]);
                }
            }
        }
    }
    __syncthreads();   // ALL reads of Xs/Wsh complete before aliased writes
    #pragma unroll
    for (int i = 0; i < 4; i++) {
        int s = ty * 4 + i;
        #pragma unroll
        for (int j = 0; j < 4; j++) Qs[s * XPAD + tx + 16 * j] = acc[i][j];
        #pragma unroll
        for (int j = 4; j < 8; j++) Ks[s * XPAD + tx + 16 * (j - 4)] = acc[i][j];
    }
    __syncthreads();

    float* attn_base = d_out + 128 + (size_t)br * FF * BB * SS * SS
                     + ((size_t)(f * BB + b)) * SS * SS;
    const float scale = 0.17677669529663687f;  // 1/sqrt(32)

    float p0[4][8];                    // head-0 probs in regs

    for (int n = 0; n < 2; n++) {
        const int off = n * 32;
        float c[4][8];
        #pragma unroll
        for (int i = 0; i < 4; i++)
            #pragma unroll
            for (int j = 0; j < 8; j++) c[i][j] = 0.f;

        // vectorized over d: 8 float4 chunks of the 32-dim head
        #pragma unroll
        for (int d4 = 0; d4 < 8; d4++) {
            float4 kv[8];
            #pragma unroll
            for (int j = 0; j < 8; j++)
                kv[j] = *(const float4*)&Ks[(tx + 16 * j) * XPAD + off + d4 * 4];
            #pragma unroll
            for (int i = 0; i < 4; i++) {
                float4 qv = *(const float4*)&Qs[(ty * 4 + i) * XPAD + off + d4 * 4];
                #pragma unroll
                for (int j = 0; j < 8; j++) {
                    c[i][j] = fmaf(qv.x, kv[j].x, c[i][j]);
                    c[i][j] = fmaf(qv.y, kv[j].y, c[i][j]);
                    c[i][j] = fmaf(qv.z, kv[j].z, c[i][j]);
                    c[i][j] = fmaf(qv.w, kv[j].w, c[i][j]);
                }
            }
        }

        // scale + row softmax (row = 16 lanes of one half-warp)
        #pragma unroll
        for (int i = 0; i < 4; i++) {
            float m = c[i][0] * scale;
            #pragma unroll
            for (int j = 0; j < 8; j++) { c[i][j] *= scale; m = fmaxf(m, c[i][j]); }
            #pragma unroll
            for (int o = 8; o >= 1; o >>= 1)
                m = fmaxf(m, __shfl_xor_sync(0xffffffffu, m, o, 16));
            float s2 = 0.f;
            #pragma unroll
            for (int j = 0; j < 8; j++) { c[i][j] = __expf(c[i][j] - m); s2 += c[i][j]; }
            #pragma unroll
            for (int o = 8; o >= 1; o >>= 1)
                s2 += __shfl_xor_sync(0xffffffffu, s2, o, 16);
            float inv = __fdividef(1.f, s2);
            #pragma unroll
            for (int j = 0; j < 8; j++) c[i][j] *= inv;
        }

        // head-mean probs: head0 in regs, single store at head1
        float colsum[8];
        #pragma unroll
        for (int j = 0; j < 8; j++) colsum[j] = 0.f;
        #pragma unroll
        for (int i = 0; i < 4; i++) {
            float* ab = attn_base + (ty * 4 + i) * SS;
            #pragma unroll
            for (int j = 0; j < 8; j++) {
                float p = c[i][j];
                colsum[j] += p;
                if (n == 0) p0[i][j] = p;
                else        ab[tx + 16 * j] = 0.5f * (p0[i][j] + p);
            }
        }
        #pragma unroll
        for (int j = 0; j < 8; j++) psum[ty * 128 + tx + 16 * j] = colsum[j];
        __syncthreads();

        if (tid < 128) {
            float s2 = 0.f;
            #pragma unroll
            for (int yy = 0; yy < 32; yy++) s2 += psum[yy * 128 + tid];
            pbar[tid] = s2 * (1.f / 128.f);
        }
        __syncthreads();

        // y = pbar @ X   (X re-read from gmem, L2-hot; dual accumulators)
        if (tid < 64) {
            float a2 = 0.f, a3 = 0.f;
            #pragma unroll 8
            for (int k = 0; k < 128; k += 2) {
                a2 = fmaf(pbar[k],     Xg[k * HH + tid],       a2);
                a3 = fmaf(pbar[k + 1], Xg[(k + 1) * HH + tid], a3);
            }
            ys[tid] = a2 + a3;
        }
        __syncthreads();

        // obar[head cols] = y @ Wv^T + bv   (Wv rows from gmem, L2-hot)
        if (tid < 32) {
            float a2 = bq[f * QN + 128 + off + tid];
            const float4* wr = (const float4*)(Wq + ((size_t)f * QN + 128 + off + tid) * HH);
            #pragma unroll
            for (int d4 = 0; d4 < 16; d4++) {
                float4 wv = wr[d4];
                a2 = fmaf(ys[d4 * 4 + 0], wv.x, a2);
                a2 = fmaf(ys[d4 * 4 + 1], wv.y, a2);
                a2 = fmaf(ys[d4 * 4 + 2], wv.z, a2);
                a2 = fmaf(ys[d4 * 4 + 3], wv.w, a2);
            }
            obar[off + tid] = a2;
        }
        __syncthreads();
    }

    // pooled = obar @ Wout^T + bout   (Wout rows from gmem, L2-hot)
    if (tid < 64) {
        float a2 = bout[f * 64 + tid];
        const float4* wr = (const float4*)(Wout + (size_t)f * 64 * 64 + tid * 64);
        #pragma unroll
        for (int h4 = 0; h4 < 16; h4++) {
            float4 wv = wr[h4];
            a2 = fmaf(obar[h4 * 4 + 0], wv.x, a2);
            a2 = fmaf(obar[h4 * 4 + 1], wv.y, a2);
            a2 = fmaf(obar[h4 * 4 + 2], wv.z, a2);
            a2 = fmaf(obar[h4 * 4 + 3], wv.w, a2);
        }
        g_comb[b][br * (FF * HH) + f * HH + tid] = a2;
    }
}

// ---------------- final: static/time MLPs + fc --------------------------------
__global__ void final_kernel(
    const float* __restrict__ stat,  // [B,32]
    const float* __restrict__ tg,    // [B,1]
    const float* __restrict__ d1w, const float* __restrict__ d1b,
    const float* __restrict__ d2w, const float* __restrict__ d2b,
    const float* __restrict__ t1w, const float* __restrict__ t1b,
    const float* __restrict__ t2w, const float* __restrict__ t2b,
    const float* __restrict__ fcw, const float* __restrict__ fcb,
    float* __restrict__ out)
{
    __shared__ float s1[64], t1s[16], tail[40], red[2][128];
    const int b = blockIdx.x, t = threadIdx.x;  // 128 threads

    if (t < 64) {
        float a = d1b[t];
        #pragma unroll
        for (int i = 0; i < 32; i++) a = fmaf(stat[b * 32 + i], d1w[t * 32 + i], a);
        s1[t] = fmaxf(a, 0.f);
    }
    if (t < 16) t1s[t] = fmaxf(fmaf(tg[b], t1w[t], t1b[t]), 0.f);
    __syncthreads();
    if (t < 32) {
        float a = d2b[t];
        #pragma unroll
        for (int i = 0; i < 64; i++) a = fmaf(s1[i], d2w[t * 64 + i], a);
        tail[t] = fmaxf(a, 0.f);
    }
    if (t >= 32 && t < 40) {
        int j = t - 32;
        float a = t2b[j];
        #pragma unroll
        for (int i = 0; i < 16; i++) a = fmaf(t1s[i], t2w[j * 16 + i], a);
        tail[t] = fmaxf(a, 0.f);
    }
    __syncthreads();

    float a0 = 0.f, a1 = 0.f;
    for (int c = t; c < 2088; c += 128) {
        float v = (c < 2048) ? g_comb[b][c] : tail[c - 2048];
        a0 = fmaf(v, fcw[c], a0);
        a1 = fmaf(v, fcw[2088 + c], a1);
    }
    red[0][t] = a0; red[1][t] = a1;
    __syncthreads();
    for (int off = 64; off >= 1; off >>= 1) {
        if (t < off) { red[0][t] += red[0][t + off]; red[1][t] += red[1][t + off]; }
        __syncthreads();
    }
    if (t == 0) {
        out[b * 2 + 0] = red[0][0] + fcb[0];
        out[b * 2 + 1] = red[1][0] + fcb[1];
    }
}

// ---------------- launch ------------------------------------------------------
extern "C" void kernel_launch(void* const* d_in, const int* in_sizes, int n_in,
                              void* d_out, int out_size)
{
    (void)in_sizes; (void)n_in; (void)out_size;
    float* out = (float*)d_out;

    cudaFuncSetAttribute(attn_kernel, cudaFuncAttributeMaxDynamicSharedMemorySize, ATTN_SMEM);

    // LSTM: both branches, batch-chunk 8 -> 256 CTAs = one full wave
    lstm_kernel<<<dim3(8, 16, 2), 256>>>(
        (const float*)d_in[0], (const float*)d_in[1],
        (const float*)d_in[4], (const float*)d_in[5],
        (const float*)d_in[6], (const float*)d_in[7],
        (const float*)d_in[8], (const float*)d_in[9],
        (const float*)d_in[10], (const float*)d_in[11]);

    // fused QK + attention (V eliminated algebraically), both branches
    attn_kernel<<<dim3(64, 16, 2), 512, ATTN_SMEM>>>(
        (const float*)d_in[12], (const float*)d_in[13],
        (const float*)d_in[14], (const float*)d_in[15],
        (const float*)d_in[16], (const float*)d_in[17],
        (const float*)d_in[18], (const float*)d_in[19],
        out);

    // final MLPs + fc
    final_kernel<<<64, 128>>>(
        (const float*)d_in[2], (const float*)d_in[3],
        (const float*)d_in[20], (const float*)d_in[21],
        (const float*)d_in[22], (const float*)d_in[23],
        (const float*)d_in[24], (const float*)d_in[25],
        (const float*)d_in[26], (const float*)d_in[27],
        (const float*)d_in[28], (const float*)d_in[29],
        out);
}

// round 15
// speedup vs baseline: 1.6868x; 1.0479x over previous
#include <cuda_runtime.h>
#include <math.h>

#define BB 64
#define SS 128
#define FF 16
#define HH 64
#define G4H 256
#define QN 192

// ---------------- scratch (static device globals; no allocation) -------------
__device__ float g_lstm[2][FF][BB][SS][HH];      // 67 MB
__device__ float g_pbar[2 * FF * BB * 2 * SS];   // 2 MB: colmean probs per head
__device__ float g_comb[BB][2 * FF * HH];        // 512 KB

// ---------------- helpers ----------------------------------------------------
__device__ __forceinline__ float sigm_f(float x) {
    return __fdividef(1.f, 1.f + __expf(-x));
}
__device__ __forceinline__ float tanh_f(float x) {
    x = fminf(fmaxf(x, -10.f), 10.f);
    float e = __expf(2.f * x);
    return __fdividef(e - 1.f, e + 1.f);
}

// ---------------- LSTM kernel (R13-passing form, untouched) -------------------
// grid (8, 16, 2): batch-chunk of 8, feature, branch. 256 threads.
#define LCH 8

__global__ void __launch_bounds__(256, 2) lstm_kernel(
    const float* __restrict__ x0, const float* __restrict__ x1,
    const float* __restrict__ Wih0, const float* __restrict__ Whh0,
    const float* __restrict__ bih0, const float* __restrict__ bhh0,
    const float* __restrict__ Wih1, const float* __restrict__ Whh1,
    const float* __restrict__ bih1, const float* __restrict__ bhh1)
{
    __shared__ float h_sh[LCH * 64];
    __shared__ float c_sh[LCH * 64];
    __shared__ float g_sh[LCH * 256];
    __shared__ float xs[LCH];

    const int t  = threadIdx.x;                 // gate index
    const int f  = blockIdx.y;
    const int b0 = blockIdx.x * LCH;
    const int br = blockIdx.z;

    const float* x   = br ? x1   : x0;
    const float* Wih = br ? Wih1 : Wih0;
    const float* Whh = br ? Whh1 : Whh0;
    const float* bih = br ? bih1 : bih0;
    const float* bhh = br ? bhh1 : bhh0;

    // register-resident Whh row for gate t (64 floats)
    float4 w[16];
    const float4* wrow = (const float4*)(Whh + (f * G4H + t) * HH);
    #pragma unroll
    for (int c = 0; c < 16; c++) w[c] = wrow[c];

    const float wih_r  = Wih[f * G4H + t];
    const float bias_r = bih[f * G4H + t] + bhh[f * G4H + t];

    for (int i = t; i < LCH * 64; i += 256) { h_sh[i] = 0.f; c_sh[i] = 0.f; }
    if (t < LCH) xs[t] = x[((b0 + t) * SS + 0) * FF + f];
    __syncthreads();

    float* outbase = &g_lstm[br][f][b0][0][0];   // [LCH][S][H] slab

    float xnext = 0.f;
    for (int s = 0; s < SS; s++) {
        // prefetch next step's x (latency hidden under the gates GEMM)
        if (t < LCH && s + 1 < SS) xnext = x[((b0 + t) * SS + s + 1) * FF + f];

        float acc[LCH];
        #pragma unroll
        for (int b = 0; b < LCH; b++) acc[b] = fmaf(xs[b], wih_r, bias_r);

        const float4* h4 = (const float4*)h_sh;
        #pragma unroll
        for (int hc = 0; hc < 16; hc++) {
            float4 wv = w[hc];
            #pragma unroll
            for (int b = 0; b < LCH; b++) {
                float4 hv = h4[b * 16 + hc];     // broadcast
                acc[b] = fmaf(wv.x, hv.x, acc[b]);
                acc[b] = fmaf(wv.y, hv.y, acc[b]);
                acc[b] = fmaf(wv.z, hv.z, acc[b]);
                acc[b] = fmaf(wv.w, hv.w, acc[b]);
            }
        }
        #pragma unroll
        for (int b = 0; b < LCH; b++) g_sh[b * 256 + t] = acc[b];
        __syncthreads();

        // epilogue: 512 cells, 2 per thread
        #pragma unroll
        for (int ci = 0; ci < 2; ci++) {
            int idx = t + ci * 256;
            int bb = idx >> 6;
            int jj = idx & 63;
            float gi = g_sh[bb * 256 + jj];
            float gf = g_sh[bb * 256 + 64 + jj];
            float gg = g_sh[bb * 256 + 128 + jj];
            float go = g_sh[bb * 256 + 192 + jj];
            float cc = sigm_f(gf) * c_sh[bb * 64 + jj] + sigm_f(gi) * tanh_f(gg);
            float hh = sigm_f(go) * tanh_f(cc);
            c_sh[bb * 64 + jj] = cc;
            h_sh[bb * 64 + jj] = hh;
            outbase[(bb * SS + s) * HH + jj] = hh;
        }
        if (t < LCH) xs[t] = xnext;
        __syncthreads();
    }
}

// ---------------- fused QK + attention core (tail stripped) -------------------
// block per (b, f, branch), 512 threads, 1 CTA/SM. Computes Q,K in-block,
// scores, softmax, head-mean probs to d_out, colmean(probs) to g_pbar. The
// pooled-output tail lives in post_kernel.
#define XPAD 68
#define ATTN_SMEM ((2*128*XPAD + 32*128) * 4)

__global__ void __launch_bounds__(512, 1) attn_kernel(
    const float* __restrict__ Wq0, const float* __restrict__ bq0,
    const float* __restrict__ Wq1, const float* __restrict__ bq1,
    float* __restrict__ d_out)
{
    extern __shared__ float sm[];
    float* Xs   = sm;                      // [128][68]   (phase 1)
    float* Wsh  = sm + 128 * XPAD;         // [128][68]   (phase 1)
    float* Qs   = sm;                      // [128][68]   (phase 2, aliases Xs)
    float* Ks   = sm + 128 * XPAD;         // [128][68]   (phase 2, aliases Wsh)
    float* psum = sm + 2 * 128 * XPAD;     // [32][128]

    const int tid = threadIdx.x;
    const int tx = tid & 15, ty = tid >> 4;   // ty: 0..31
    const int b = blockIdx.x, f = blockIdx.y, br = blockIdx.z;

    const float* Wq = br ? Wq1 : Wq0;
    const float* bq = br ? bq1 : bq0;

    const float* Xg = &g_lstm[br][f][b][0][0];     // [128][64] in gmem

    // ---- stage X [128][64] and Wqk [128][64] ----
    const float4* X4 = (const float4*)Xg;
    #pragma unroll
    for (int l = 0; l < 4; l++) {
        int li = tid + l * 512;              // 0..2047
        int s = li >> 4, c4 = li & 15;
        *(float4*)&Xs[s * XPAD + c4 * 4] = X4[li];
    }
    const float4* W4 = (const float4*)(Wq + (size_t)f * QN * HH);
    #pragma unroll
    for (int l = 0; l < 4; l++) {
        int li = tid + l * 512;              // rows 0..127 (Q,K)
        int g = li >> 4, c4 = li & 15;
        *(float4*)&Wsh[g * XPAD + c4 * 4] = W4[li];
    }
    __syncthreads();

    // ---- QK GEMM: [128 rows][128 gate-cols], acc held across the barrier ----
    float acc[4][8];
    {
        #pragma unroll
        for (int j = 0; j < 8; j++) {
            float bj = bq[f * QN + tx + 16 * j];
            #pragma unroll
            for (int i = 0; i < 4; i++) acc[i][j] = bj;
        }
        #pragma unroll
        for (int k4 = 0; k4 < 16; k4++) {
            float4 wv[8];
            #pragma unroll
            for (int j = 0; j < 8; j++)
                wv[j] = *(const float4*)&Wsh[(tx + 16 * j) * XPAD + k4 * 4];
            #pragma unroll
            for (int i = 0; i < 4; i++) {
                float4 xv = *(const float4*)&Xs[(ty * 4 + i) * XPAD + k4 * 4];
                #pragma unroll
                for (int j = 0; j < 8; j++) {
                    acc[i][j] = fmaf(xv.x, wv[j].x, acc[i][j]);
                    acc[i][j] = fmaf(xv.y, wv[j].y, acc[i][j]);
                    acc[i][j] = fmaf(xv.z, wv[j].z, acc[i][j]);
                    acc[i][j] = fmaf(xv.w, wv[j].w, acc[i][j]);
                }
            }
        }
    }
    __syncthreads();   // ALL reads of Xs/Wsh complete before aliased writes
    #pragma unroll
    for (int i = 0; i < 4; i++) {
        int s = ty * 4 + i;
        #pragma unroll
        for (int j = 0; j < 4; j++) Qs[s * XPAD + tx + 16 * j] = acc[i][j];
        #pragma unroll
        for (int j = 4; j < 8; j++) Ks[s * XPAD + tx + 16 * (j - 4)] = acc[i][j];
    }
    __syncthreads();

    float* attn_base = d_out + 128 + (size_t)br * FF * BB * SS * SS
                     + ((size_t)(f * BB + b)) * SS * SS;
    const float scale = 0.17677669529663687f;  // 1/sqrt(32)

    float p0[4][8];                    // head-0 probs in regs

    for (int n = 0; n < 2; n++) {
        const int off = n * 32;
        float c[4][8];
        #pragma unroll
        for (int i = 0; i < 4; i++)
            #pragma unroll
            for (int j = 0; j < 8; j++) c[i][j] = 0.f;

        // vectorized over d: 8 float4 chunks of the 32-dim head
        #pragma unroll
        for (int d4 = 0; d4 < 8; d4++) {
            float4 kv[8];
            #pragma unroll
            for (int j = 0; j < 8; j++)
                kv[j] = *(const float4*)&Ks[(tx + 16 * j) * XPAD + off + d4 * 4];
            #pragma unroll
            for (int i = 0; i < 4; i++) {
                float4 qv = *(const float4*)&Qs[(ty * 4 + i) * XPAD + off + d4 * 4];
                #pragma unroll
                for (int j = 0; j < 8; j++) {
                    c[i][j] = fmaf(qv.x, kv[j].x, c[i][j]);
                    c[i][j] = fmaf(qv.y, kv[j].y, c[i][j]);
                    c[i][j] = fmaf(qv.z, kv[j].z, c[i][j]);
                    c[i][j] = fmaf(qv.w, kv[j].w, c[i][j]);
                }
            }
        }

        // scale + row softmax (row = 16 lanes of one half-warp)
        #pragma unroll
        for (int i = 0; i < 4; i++) {
            float m = c[i][0] * scale;
            #pragma unroll
            for (int j = 0; j < 8; j++) { c[i][j] *= scale; m = fmaxf(m, c[i][j]); }
            #pragma unroll
            for (int o = 8; o >= 1; o >>= 1)
                m = fmaxf(m, __shfl_xor_sync(0xffffffffu, m, o, 16));
            float s2 = 0.f;
            #pragma unroll
            for (int j = 0; j < 8; j++) { c[i][j] = __expf(c[i][j] - m); s2 += c[i][j]; }
            #pragma unroll
            for (int o = 8; o >= 1; o >>= 1)
                s2 += __shfl_xor_sync(0xffffffffu, s2, o, 16);
            float inv = __fdividef(1.f, s2);
            #pragma unroll
            for (int j = 0; j < 8; j++) c[i][j] *= inv;
        }

        // head-mean probs: head0 in regs, single store at head1
        float colsum[8];
        #pragma unroll
        for (int j = 0; j < 8; j++) colsum[j] = 0.f;
        #pragma unroll
        for (int i = 0; i < 4; i++) {
            float* ab = attn_base + (ty * 4 + i) * SS;
            #pragma unroll
            for (int j = 0; j < 8; j++) {
                float p = c[i][j];
                colsum[j] += p;
                if (n == 0) p0[i][j] = p;
                else        ab[tx + 16 * j] = 0.5f * (p0[i][j] + p);
            }
        }
        #pragma unroll
        for (int j = 0; j < 8; j++) psum[ty * 128 + tx + 16 * j] = colsum[j];
        __syncthreads();

        // colmean to gmem (post_kernel consumes)
        if (tid < 128) {
            float s2 = 0.f;
            #pragma unroll
            for (int yy = 0; yy < 32; yy++) s2 += psum[yy * 128 + tid];
            g_pbar[((((size_t)br * FF + f) * BB + b) * 2 + n) * SS + tid]
                = s2 * (1.f / 128.f);
        }
        __syncthreads();   // psum reused by next head
    }
}

// ---------------- post: pooled = ((pbar @ X) @ Wv^T + bv) @ Wout^T + bout -----
// grid (64, 16, 2), 128 threads. All phases full-ish width, coalesced X reads.
__global__ void __launch_bounds__(128) post_kernel(
    const float* __restrict__ Wq0, const float* __restrict__ bq0,
    const float* __restrict__ Wo0, const float* __restrict__ bo0,
    const float* __restrict__ Wq1, const float* __restrict__ bq1,
    const float* __restrict__ Wo1, const float* __restrict__ bo1)
{
    __shared__ float ys[2][64];
    __shared__ float obar[64];

    const int tid = threadIdx.x;
    const int b = blockIdx.x, f = blockIdx.y, br = blockIdx.z;

    const float* Wq   = br ? Wq1 : Wq0;
    const float* bq   = br ? bq1 : bq0;
    const float* Wout = br ? Wo1 : Wo0;
    const float* bout = br ? bo1 : bo0;

    const float* Xg = &g_lstm[br][f][b][0][0];     // [128][64]
    const float* pb = &g_pbar[(((size_t)br * FF + f) * BB + b) * 2 * SS];

    // ys[h][d] = sum_k pbar[h][k] * X[k][d]   (threads: h = tid>>6, d = tid&63)
    {
        const int h = tid >> 6, d = tid & 63;
        const float* p = pb + h * SS;
        float a2 = 0.f, a3 = 0.f;
        #pragma unroll 8
        for (int k = 0; k < 128; k += 2) {
            a2 = fmaf(p[k],     Xg[k * HH + d],       a2);
            a3 = fmaf(p[k + 1], Xg[(k + 1) * HH + d], a3);
        }
        ys[h][d] = a2 + a3;
    }
    __syncthreads();

    // obar[c] = ys[c/32] . Wv_row(128+c) + bv[c]
    if (tid < 64) {
        const int h = tid >> 5;
        float a2 = bq[f * QN + 128 + tid];
        const float4* wr = (const float4*)(Wq + ((size_t)f * QN + 128 + tid) * HH);
        #pragma unroll
        for (int d4 = 0; d4 < 16; d4++) {
            float4 wv = wr[d4];
            a2 = fmaf(ys[h][d4 * 4 + 0], wv.x, a2);
            a2 = fmaf(ys[h][d4 * 4 + 1], wv.y, a2);
            a2 = fmaf(ys[h][d4 * 4 + 2], wv.z, a2);
            a2 = fmaf(ys[h][d4 * 4 + 3], wv.w, a2);
        }
        obar[tid] = a2;
    }
    __syncthreads();

    // pooled = obar @ Wout^T + bout
    if (tid < 64) {
        float a2 = bout[f * 64 + tid];
        const float4* wr = (const float4*)(Wout + (size_t)f * 64 * 64 + tid * 64);
        #pragma unroll
        for (int h4 = 0; h4 < 16; h4++) {
            float4 wv = wr[h4];
            a2 = fmaf(obar[h4 * 4 + 0], wv.x, a2);
            a2 = fmaf(obar[h4 * 4 + 1], wv.y, a2);
            a2 = fmaf(obar[h4 * 4 + 2], wv.z, a2);
            a2 = fmaf(obar[h4 * 4 + 3], wv.w, a2);
        }
        g_comb[b][br * (FF * HH) + f * HH + tid] = a2;
    }
}

// ---------------- final: static/time MLPs + fc --------------------------------
__global__ void final_kernel(
    const float* __restrict__ stat,  // [B,32]
    const float* __restrict__ tg,    // [B,1]
    const float* __restrict__ d1w, const float* __restrict__ d1b,
    const float* __restrict__ d2w, const float* __restrict__ d2b,
    const float* __restrict__ t1w, const float* __restrict__ t1b,
    const float* __restrict__ t2w, const float* __restrict__ t2b,
    const float* __restrict__ fcw, const float* __restrict__ fcb,
    float* __restrict__ out)
{
    __shared__ float s1[64], t1s[16], tail[40], red[2][128];
    const int b = blockIdx.x, t = threadIdx.x;  // 128 threads

    if (t < 64) {
        float a = d1b[t];
        #pragma unroll
        for (int i = 0; i < 32; i++) a = fmaf(stat[b * 32 + i], d1w[t * 32 + i], a);
        s1[t] = fmaxf(a, 0.f);
    }
    if (t < 16) t1s[t] = fmaxf(fmaf(tg[b], t1w[t], t1b[t]), 0.f);
    __syncthreads();
    if (t < 32) {
        float a = d2b[t];
        #pragma unroll
        for (int i = 0; i < 64; i++) a = fmaf(s1[i], d2w[t * 64 + i], a);
        tail[t] = fmaxf(a, 0.f);
    }
    if (t >= 32 && t < 40) {
        int j = t - 32;
        float a = t2b[j];
        #pragma unroll
        for (int i = 0; i < 16; i++) a = fmaf(t1s[i], t2w[j * 16 + i], a);
        tail[t] = fmaxf(a, 0.f);
    }
    __syncthreads();

    float a0 = 0.f, a1 = 0.f;
    for (int c = t; c < 2088; c += 128) {
        float v = (c < 2048) ? g_comb[b][c] : tail[c - 2048];
        a0 = fmaf(v, fcw[c], a0);
        a1 = fmaf(v, fcw[2088 + c], a1);
    }
    red[0][t] = a0; red[1][t] = a1;
    __syncthreads();
    for (int off = 64; off >= 1; off >>= 1) {
        if (t < off) { red[0][t] += red[0][t + off]; red[1][t] += red[1][t + off]; }
        __syncthreads();
    }
    if (t == 0) {
        out[b * 2 + 0] = red[0][0] + fcb[0];
        out[b * 2 + 1] = red[1][0] + fcb[1];
    }
}

// ---------------- launch ------------------------------------------------------
extern "C" void kernel_launch(void* const* d_in, const int* in_sizes, int n_in,
                              void* d_out, int out_size)
{
    (void)in_sizes; (void)n_in; (void)out_size;
    float* out = (float*)d_out;

    cudaFuncSetAttribute(attn_kernel, cudaFuncAttributeMaxDynamicSharedMemorySize, ATTN_SMEM);

    // LSTM: both branches, batch-chunk 8 -> 256 CTAs = one full wave
    lstm_kernel<<<dim3(8, 16, 2), 256>>>(
        (const float*)d_in[0], (const float*)d_in[1],
        (const float*)d_in[4], (const float*)d_in[5],
        (const float*)d_in[6], (const float*)d_in[7],
        (const float*)d_in[8], (const float*)d_in[9],
        (const float*)d_in[10], (const float*)d_in[11]);

    // fused QK + attention: probs + colmean only
    attn_kernel<<<dim3(64, 16, 2), 512, ATTN_SMEM>>>(
        (const float*)d_in[12], (const float*)d_in[13],
        (const float*)d_in[16], (const float*)d_in[17],
        out);

    // pooled tail (V-elimination algebra), full-width threads
    post_kernel<<<dim3(64, 16, 2), 128>>>(
        (const float*)d_in[12], (const float*)d_in[13],
        (const float*)d_in[14], (const float*)d_in[15],
        (const float*)d_in[16], (const float*)d_in[17],
        (const float*)d_in[18], (const float*)d_in[19]);

    // final MLPs + fc
    final_kernel<<<64, 128>>>(
        (const float*)d_in[2], (const float*)d_in[3],
        (const float*)d_in[20], (const float*)d_in[21],
        (const float*)d_in[22], (const float*)d_in[23],
        (const float*)d_in[24], (const float*)d_in[25],
        (const float*)d_in[26], (const float*)d_in[27],
        (const float*)d_in[28], (const float*)d_in[29],
        out);
}